// round 12
// baseline (speedup 1.0000x reference)
#include <cuda_runtime.h>
#include <cstdint>

constexpr int N = 64, C = 256, S = 30, HW = 176;
constexpr int CSTR = S * HW, NSTR = C * CSTR;
constexpr int R = 8, TOPK = 10;
constexpr int H = 8;                      // hw per block (32B coalesced rows)
constexpr int CI = 64, NIT = 4;           // channels per iteration
constexpr int SLOTS = CI + 2 * R;         // 80 resident slots (circular halo)
constexpr int SP = 84;                    // words per (s,hw) slot-row: conflict-free
constexpr int SCH = 10, NCH = 3;          // s-chunks for load/compute overlap
constexpr int SMEMB = S * H * SP * 4;     // 80640 B -> 2 blocks/SM

__device__ float d_g[R + 1];

// g[d] = (1/256)(1 + 2*sum_{k=1..127} e^{-k^2/2048} cos(pi k d/128) + e^{-8} cos(pi d))
__global__ void kinit() {
    const int d = blockIdx.x, t = threadIdx.x;
    const double PI = 3.14159265358979323846;
    double k = (double)(t + 1);
    double term = exp(-k * k / 2048.0) * cos(PI * k * (double)d / 128.0);
    if (t != 127) term *= 2.0;            // Nyquist (k=128) counted once
    __shared__ double red[4];
    #pragma unroll
    for (int o = 16; o; o >>= 1) term += __shfl_down_sync(0xffffffffu, term, o);
    if ((t & 31) == 0) red[t >> 5] = term;
    __syncthreads();
    if (t == 0) d_g[d] = (float)((1.0 + red[0] + red[1] + red[2] + red[3]) / 256.0);
}

// Packed f32x2 helpers (lane-wise rounding identical to scalar fmaf/fadd/fmul)
__device__ __forceinline__ uint64_t pk2(float x, float y) {
    uint64_t r; asm("mov.b64 %0,{%1,%2};" : "=l"(r) : "f"(x), "f"(y)); return r;
}
__device__ __forceinline__ void upk2(uint64_t u, float& x, float& y) {
    asm("mov.b64 {%0,%1},%2;" : "=f"(x), "=f"(y) : "l"(u));
}
__device__ __forceinline__ uint64_t fma2_(uint64_t a, uint64_t b, uint64_t c) {
    uint64_t d; asm("fma.rn.f32x2 %0,%1,%2,%3;" : "=l"(d) : "l"(a), "l"(b), "l"(c)); return d;
}
__device__ __forceinline__ uint64_t add2_(uint64_t a, uint64_t b) {
    uint64_t d; asm("add.rn.f32x2 %0,%1,%2;" : "=l"(d) : "l"(a), "l"(b)); return d;
}
__device__ __forceinline__ uint64_t mul2_(uint64_t a, uint64_t b) {
    uint64_t d; asm("mul.rn.f32x2 %0,%1,%2;" : "=l"(d) : "l"(a), "l"(b)); return d;
}

__global__ void __launch_bounds__(256, 2)
kfused(const float* __restrict__ seqs, const float* __restrict__ flogit,
       float* __restrict__ out) {
    extern __shared__ float sm[];
    const uint32_t smu = (uint32_t)__cvta_generic_to_shared(sm);
    const int hw0 = blockIdx.x * H;
    const int n   = blockIdx.y;
    const int tid = threadIdx.x;
    const int hw  = tid & 7;
    const int cg  = tid >> 3;             // 0..31 -> local channels 2cg, 2cg+1
    const int w0  = 2 * cg;               // window base slot (8B aligned)
    const float alpha = 1.0f / (1.0f + expf(-flogit[0]));

    uint64_t gg[R + 1];
    #pragma unroll
    for (int d = 0; d <= R; ++d) { float g = d_g[d]; gg[d] = pk2(g, g); }

    #pragma unroll 1
    for (int it = 0; it < NIT; ++it) {
        const int cb = it * CI + C - R;   // slot -> channel (cb+slot)&255

        // Issue 3 s-chunk load groups: 4B cp.async, lanes hw-consecutive
        // (8 lanes = one 32B src sector); dst is slot-major transposed tile.
        #pragma unroll
        for (int ck = 0; ck < NCH; ++ck) {
            #pragma unroll 1
            for (int j = 0; j < (SLOTS * SCH * H) / 256; ++j) {   // 25
                int i = tid + j * 256;
                int hwl  = i & 7;
                int r    = i >> 3;              // 0..799
                int sl   = r / SLOTS;
                int slot = r - sl * SLOTS;
                int s    = ck * SCH + sl;
                int c    = (cb + slot) & 255;
                const float* src = seqs + (size_t)n * NSTR + (size_t)c * CSTR
                                   + s * HW + hw0 + hwl;
                uint32_t dst = smu + (((s * H + hwl) * SP + slot) << 2);
                asm volatile("cp.async.ca.shared.global [%0],[%1],4;"
                             :: "r"(dst), "l"(src));
            }
            asm volatile("cp.async.commit_group;" ::: "memory");
        }

        float sc[2][S], top[2][TOPK];
        #pragma unroll
        for (int ch = 0; ch < 2; ++ch)
            #pragma unroll
            for (int i = 0; i < TOPK; ++i) top[ch][i] = -1.0f;

        // Compute chunk k while chunk k+1 streams in
        #pragma unroll
        for (int ck = 0; ck < NCH; ++ck) {
            if (ck == 0)      asm volatile("cp.async.wait_group 2;" ::: "memory");
            else if (ck == 1) asm volatile("cp.async.wait_group 1;" ::: "memory");
            else              asm volatile("cp.async.wait_group 0;" ::: "memory");
            __syncthreads();

            #pragma unroll
            for (int j = 0; j < SCH; ++j) {
                const int s = ck * SCH + j;
                const float* b = sm + (s * H + hw) * SP + w0;
                float2 w2[9];                       // slots w0..w0+17 as pairs
                #pragma unroll
                for (int u = 0; u < 9; ++u)
                    w2[u] = *reinterpret_cast<const float2*>(b + 2 * u);
                // scalar view of the window
                #define Wj(j_) (((j_) & 1) ? w2[(j_) >> 1].y : w2[(j_) >> 1].x)
                // packed conv, accumulation order d=1..8 (identical to scalar)
                uint64_t acc = mul2_(gg[0], pk2(w2[4].x, w2[4].y));
                #pragma unroll
                for (int d = 1; d <= R; ++d)
                    acc = fma2_(gg[d],
                                add2_(pk2(Wj(8 - d), Wj(9 - d)),
                                      pk2(Wj(8 + d), Wj(9 + d))), acc);
                float a0, a1; upk2(acc, a0, a1);
                const float x0 = w2[4].x, x1 = w2[4].y;
                const float sv0 = __fdividef(fabsf(a0), fabsf(a0 - x0) + 1e-6f);
                const float sv1 = __fdividef(fabsf(a1), fabsf(a1 - x1) + 1e-6f);
                sc[0][s] = sv0; sc[1][s] = sv1;
                float cr0 = sv0, cr1 = sv1;        // triangular insertion chains
                #pragma unroll
                for (int i = 0; i < TOPK; ++i) {
                    if (i <= s) {
                        float m0 = fmaxf(top[0][i], cr0);
                        cr0      = fminf(top[0][i], cr0);
                        top[0][i] = m0;
                        float m1 = fmaxf(top[1][i], cr1);
                        cr1      = fminf(top[1][i], cr1);
                        top[1][i] = m1;
                    }
                }
                #undef Wj
            }
        }

        // Threshold + stable-tie selection + max pool + fused output
        const float thr0 = top[0][TOPK - 1], thr1 = top[1][TOPK - 1];
        int bud0 = TOPK, bud1 = TOPK;
        #pragma unroll
        for (int s = 0; s < S; ++s) {
            bud0 -= (sc[0][s] > thr0);
            bud1 -= (sc[1][s] > thr1);
        }
        float sum0 = 0.0f, sum1 = 0.0f, mx0 = -3.0e38f, mx1 = -3.0e38f;
        #pragma unroll
        for (int s = 0; s < S; ++s) {
            const float2 v2 = *reinterpret_cast<const float2*>(
                sm + (s * H + hw) * SP + w0 + R);   // slots w0+8, w0+9
            mx0 = fmaxf(mx0, v2.x);
            mx1 = fmaxf(mx1, v2.y);
            bool t0 = sc[0][s] > thr0;
            if (sc[0][s] == thr0 && bud0 > 0) { t0 = true; --bud0; }
            if (t0) sum0 += v2.x;
            bool t1 = sc[1][s] > thr1;
            if (sc[1][s] == thr1 && bud1 > 0) { t1 = true; --bud1; }
            if (t1) sum1 += v2.y;
        }
        const int c0 = it * CI + 2 * cg;
        out[(n * C + c0) * HW + hw0 + hw] =
            alpha * (sum0 * (1.0f / TOPK)) + (1.0f - alpha) * mx0;
        out[(n * C + c0 + 1) * HW + hw0 + hw] =
            alpha * (sum1 * (1.0f / TOPK)) + (1.0f - alpha) * mx1;

        __syncthreads();   // tile reads done before next iteration overwrites
    }
}

extern "C" void kernel_launch(void* const* d_in, const int* in_sizes, int n_in,
                              void* d_out, int out_size) {
    const float* seqs  = (const float*)d_in[0];
    const float* logit = (const float*)d_in[1];
    float* out = (float*)d_out;
    cudaFuncSetAttribute(kfused, cudaFuncAttributeMaxDynamicSharedMemorySize, SMEMB);
    kinit<<<R + 1, 128>>>();
    kfused<<<dim3(HW / H, N), 256, SMEMB>>>(seqs, logit, out);
}

// round 14
// speedup vs baseline: 1.3264x; 1.3264x over previous
#include <cuda_runtime.h>
#include <cstdint>

constexpr int N = 64, C = 256, S = 30, HW = 176;
constexpr int CSTR = S * HW, NSTR = C * CSTR;
constexpr int R = 8, TOPK = 10;
constexpr int H = 8;                      // hw per block: 32B rows, sector-aligned
constexpr int CI = 64, NIT = 4;           // channels per iteration
constexpr int SLOTS = CI + 2 * R;         // 80 (circular halo)
constexpr int P = 12;                     // pitch words: 8 hw + 4 pad, conflict-free
constexpr int SCH = 10, NCH = 3;          // s-chunks for load/compute overlap
// Trim unreachable tail padding of the last row so 2 blocks fit in 227KB/SM.
constexpr int SMEMW = S * SLOTS * P - (P - H);
constexpr int SMEMB = SMEMW * 4;          // 115184 B -> 2 blocks/SM

__device__ float d_g[R + 1];

// g[d] = (1/256)(1 + 2*sum_{k=1..127} e^{-k^2/2048} cos(pi k d/128) + e^{-8} cos(pi d))
__global__ void kinit() {
    const int d = blockIdx.x, t = threadIdx.x;
    const double PI = 3.14159265358979323846;
    double k = (double)(t + 1);
    double term = exp(-k * k / 2048.0) * cos(PI * k * (double)d / 128.0);
    if (t != 127) term *= 2.0;            // Nyquist (k=128) counted once
    __shared__ double red[4];
    #pragma unroll
    for (int o = 16; o; o >>= 1) term += __shfl_down_sync(0xffffffffu, term, o);
    if ((t & 31) == 0) red[t >> 5] = term;
    __syncthreads();
    if (t == 0) d_g[d] = (float)((1.0 + red[0] + red[1] + red[2] + red[3]) / 256.0);
}

__global__ void __launch_bounds__(256, 2)
kfused(const float* __restrict__ seqs, const float* __restrict__ flogit,
       float* __restrict__ out) {
    extern __shared__ float sm[];
    const int hw0 = blockIdx.x * H;
    const int n   = blockIdx.y;
    const int tid = threadIdx.x;
    const int hw  = tid & 7;
    const int cg  = tid >> 3;             // 0..31 -> local channels 2cg, 2cg+1
    const int w0  = 2 * cg;               // window base slot
    const float alpha = 1.0f / (1.0f + expf(-flogit[0]));

    float g[R + 1];
    #pragma unroll
    for (int d = 0; d <= R; ++d) g[d] = d_g[d];

    #pragma unroll 1
    for (int it = 0; it < NIT; ++it) {
        const int cb = it * CI + C - R;   // slot -> channel (cb+slot)&255

        // Issue all 3 s-chunk load groups (two 16B cp.asyncs per 32B row;
        // pitch-12 rows are 48B-spaced -> both 16B-aligned).
        // SLOTS*SCH*2 = 1600 = 6*256 + 64: 6 uniform rounds + 64-thread tail.
        #pragma unroll
        for (int ck = 0; ck < NCH; ++ck) {
            #pragma unroll
            for (int j = 0; j < 7; ++j) {
                int i = tid + j * 256;
                if (j == 6 && tid >= 64) break;
                int q = i & 1, r = i >> 1;
                int sl = r / SLOTS, slot = r - sl * SLOTS;
                int s = ck * SCH + sl;
                int c = (cb + slot) & 255;
                const float* src = seqs + (size_t)n * NSTR + (size_t)c * CSTR
                                   + s * HW + hw0 + q * 4;
                uint32_t dst = (uint32_t)__cvta_generic_to_shared(
                    sm + (s * SLOTS + slot) * P + q * 4);
                asm volatile("cp.async.cg.shared.global [%0],[%1],16;"
                             :: "r"(dst), "l"(src));
            }
            asm volatile("cp.async.commit_group;" ::: "memory");
        }

        float sc[2][S], top[2][TOPK];
        #pragma unroll
        for (int ch = 0; ch < 2; ++ch)
            #pragma unroll
            for (int i = 0; i < TOPK; ++i) top[ch][i] = -1.0f;

        // Compute chunk k while chunk k+1 streams in
        #pragma unroll
        for (int ck = 0; ck < NCH; ++ck) {
            if (ck == 0)      asm volatile("cp.async.wait_group 2;" ::: "memory");
            else if (ck == 1) asm volatile("cp.async.wait_group 1;" ::: "memory");
            else              asm volatile("cp.async.wait_group 0;" ::: "memory");
            __syncthreads();

            #pragma unroll
            for (int j = 0; j < SCH; ++j) {
                const int s = ck * SCH + j;
                const float* b = sm + (s * SLOTS + w0) * P + hw;
                float w[2 * R + 2];
                #pragma unroll
                for (int u = 0; u < 2 * R + 2; ++u) w[u] = b[u * P];
                #pragma unroll
                for (int ch = 0; ch < 2; ++ch) {
                    const float x = w[ch + R];
                    float acc = g[0] * x;
                    #pragma unroll
                    for (int d = 1; d <= R; ++d)
                        acc = fmaf(g[d], w[ch + R - d] + w[ch + R + d], acc);
                    const float sv = __fdividef(fabsf(acc), fabsf(acc - x) + 1e-6f);
                    sc[ch][s] = sv;
                    float cr = sv;             // triangular insertion chain
                    #pragma unroll
                    for (int i = 0; i < TOPK; ++i) {
                        if (i <= s) {
                            float m = fmaxf(top[ch][i], cr);
                            cr      = fminf(top[ch][i], cr);
                            top[ch][i] = m;
                        }
                    }
                }
            }
        }

        // Thresholds; strict-greater count derived from top[] itself:
        // any sc > thr is necessarily one of the kept top-10 entries.
        const float thr0 = top[0][TOPK - 1], thr1 = top[1][TOPK - 1];
        int bud0 = TOPK, bud1 = TOPK;
        #pragma unroll
        for (int i = 0; i < TOPK - 1; ++i) {
            bud0 -= (top[0][i] > thr0);
            bud1 -= (top[1][i] > thr1);
        }

        // Single merged pass: stable-tie selection + max pool, both channels
        float sum0 = 0.0f, sum1 = 0.0f, mx0 = -3.0e38f, mx1 = -3.0e38f;
        const float* p0 = sm + (w0 + R) * P + hw;      // slot w0+8, s=0
        #pragma unroll
        for (int s = 0; s < S; ++s) {
            const float v0 = p0[0];
            const float v1 = p0[P];                    // slot w0+9
            p0 += SLOTS * P;
            mx0 = fmaxf(mx0, v0);
            mx1 = fmaxf(mx1, v1);
            bool t0 = sc[0][s] > thr0;
            if (sc[0][s] == thr0 && bud0 > 0) { t0 = true; --bud0; }
            if (t0) sum0 += v0;
            bool t1 = sc[1][s] > thr1;
            if (sc[1][s] == thr1 && bud1 > 0) { t1 = true; --bud1; }
            if (t1) sum1 += v1;
        }
        const int c0 = it * CI + 2 * cg;
        out[(n * C + c0) * HW + hw0 + hw] =
            alpha * (sum0 * (1.0f / TOPK)) + (1.0f - alpha) * mx0;
        out[(n * C + c0 + 1) * HW + hw0 + hw] =
            alpha * (sum1 * (1.0f / TOPK)) + (1.0f - alpha) * mx1;

        __syncthreads();   // tile reads done before next iteration overwrites
    }
}

extern "C" void kernel_launch(void* const* d_in, const int* in_sizes, int n_in,
                              void* d_out, int out_size) {
    const float* seqs  = (const float*)d_in[0];
    const float* logit = (const float*)d_in[1];
    float* out = (float*)d_out;
    cudaFuncSetAttribute(kfused, cudaFuncAttributeMaxDynamicSharedMemorySize, SMEMB);
    kinit<<<R + 1, 128>>>();
    kfused<<<dim3(HW / H, N), 256, SMEMB>>>(seqs, logit, out);
}